// round 9
// baseline (speedup 1.0000x reference)
#include <cuda_runtime.h>

#define B_    2048
#define T_    128
#define V_    256
#define H_    20
#define G3_   60
#define L_    15
#define NBW   4
#define GRID  (B_ / NBW)

typedef unsigned long long u64;

__device__ __forceinline__ u64 pk(float lo, float hi) {
    u64 r; asm("mov.b64 %0,{%1,%2};" : "=l"(r) : "f"(lo), "f"(hi)); return r;
}
__device__ __forceinline__ void upk(float& lo, float& hi, u64 v) {
    asm("mov.b64 {%0,%1},%2;" : "=f"(lo), "=f"(hi) : "l"(v));
}
__device__ __forceinline__ u64 f2fma(u64 a, u64 b, u64 c) {
    u64 d; asm("fma.rn.f32x2 %0,%1,%2,%3;" : "=l"(d) : "l"(a), "l"(b), "l"(c)); return d;
}
__device__ __forceinline__ u64 f2add(u64 a, u64 b) {
    u64 d; asm("add.rn.f32x2 %0,%1,%2;" : "=l"(d) : "l"(a), "l"(b)); return d;
}
__device__ __forceinline__ float fsigm(float x) {
    return __fdividef(1.0f, 1.0f + __expf(-x));
}
__device__ __forceinline__ float ftanh_(float x) {
    float e = __expf(2.0f * x);
    return 1.0f - __fdividef(2.0f, e + 1.0f);
}

__global__ __launch_bounds__(32)
void gru2_kernel(const int* __restrict__ x,
                 const float* __restrict__ W0, const float* __restrict__ U0,
                 const float* __restrict__ b0i, const float* __restrict__ b0r,
                 const float* __restrict__ W1, const float* __restrict__ U1,
                 const float* __restrict__ b1i, const float* __restrict__ b1r,
                 const float* __restrict__ Wd, const float* __restrict__ bd,
                 float* __restrict__ out)
{
    // j-pair packed weights: u64 = {w[k][2jp], w[k][2jp+1]}, k contiguous, row pad 22
    __shared__ alignas(16) u64 WL0[3][10][22];   // U0 z,r,h
    __shared__ alignas(16) u64 WL1[6][10][22];   // W1 z,r,h ; U1 z,r,h
    // dup-packed h {h,h} per k; [buf][batch][k], row 24 u64 (192B: bank-parallel)
    __shared__ alignas(16) u64 h0d[2][NBW][24];
    __shared__ alignas(16) u64 h1d[2][NBW][24];
    __shared__ int   xs[NBW][T_];
    __shared__ float lgs[NBW][16];

    const int lane = threadIdx.x & 31;
    const int l2   = (lane < 20) ? lane : lane - 20;
    const int cp   = l2 / 10;
    const int jp   = l2 % 10;
    const int cA   = cp, cB = cp + 2;
    const int b0g  = blockIdx.x * NBW;
    const int j0   = 2 * jp, j1 = 2 * jp + 1;

    for (int idx = lane; idx < 600; idx += 32) {
        int g = idx / 200, rem = idx % 200, jj = rem / 20, k = rem % 20;
        WL0[g][jj][k] = pk(U0[k * G3_ + g * H_ + 2 * jj],
                           U0[k * G3_ + g * H_ + 2 * jj + 1]);
    }
    for (int idx = lane; idx < 1200; idx += 32) {
        int g = idx / 200, rem = idx % 200, jj = rem / 20, k = rem % 20;
        const float* M = (g < 3) ? W1 : U1;
        int gg = (g < 3) ? g : g - 3;
        WL1[g][jj][k] = pk(M[k * G3_ + gg * H_ + 2 * jj],
                           M[k * G3_ + gg * H_ + 2 * jj + 1]);
    }
    for (int idx = lane; idx < NBW * T_; idx += 32) {
        int c = idx >> 7, t = idx & (T_ - 1);
        xs[c][t] = x[(b0g + c) * T_ + t];
    }
    for (int idx = lane; idx < 2 * NBW * 24; idx += 32) {
        (&h0d[0][0][0])[idx] = 0ull;
        (&h1d[0][0][0])[idx] = 0ull;
    }

    const u64 zc0   = pk(b0i[j0] + b0r[j0],       b0i[j1] + b0r[j1]);
    const u64 rc0   = pk(b0i[20+j0] + b0r[20+j0], b0i[20+j1] + b0r[20+j1]);
    const u64 bh0r2 = pk(b0r[40+j0],              b0r[40+j1]);
    const u64 bh0i2 = pk(b0i[40+j0],              b0i[40+j1]);
    const u64 zc1   = pk(b1i[j0] + b1r[j0],       b1i[j1] + b1r[j1]);
    const u64 rc1   = pk(b1i[20+j0] + b1r[20+j0], b1i[20+j1] + b1r[20+j1]);
    const u64 bxh1  = pk(b1i[40+j0],              b1i[40+j1]);
    const u64 brh1  = pk(b1r[40+j0],              b1r[40+j1]);
    __syncwarp();

    const ulonglong2* pWz = (const ulonglong2*)&WL0[0][jp][0];
    const ulonglong2* pWr = (const ulonglong2*)&WL0[1][jp][0];
    const ulonglong2* pWh = (const ulonglong2*)&WL0[2][jp][0];
    const ulonglong2* pVz = (const ulonglong2*)&WL1[0][jp][0];
    const ulonglong2* pVr = (const ulonglong2*)&WL1[1][jp][0];
    const ulonglong2* pVh = (const ulonglong2*)&WL1[2][jp][0];
    const ulonglong2* pUz = (const ulonglong2*)&WL1[3][jp][0];
    const ulonglong2* pUr = (const ulonglong2*)&WL1[4][jp][0];
    const ulonglong2* pUh = (const ulonglong2*)&WL1[5][jp][0];

    float h0A0 = 0.f, h0A1 = 0.f, h0B0 = 0.f, h0B1 = 0.f;
    float h1A0 = 0.f, h1A1 = 0.f, h1B0 = 0.f, h1B1 = 0.f;

    u64 xwzA, xwrA, xwhA, xwzB, xwrB, xwhB;
    {
        const float* rA = W0 + xs[cA][0] * G3_;
        const float* rB = W0 + xs[cB][0] * G3_;
        float2 a0 = *(const float2*)(rA + j0);
        float2 a1 = *(const float2*)(rA + 20 + j0);
        float2 a2 = *(const float2*)(rA + 40 + j0);
        float2 c0 = *(const float2*)(rB + j0);
        float2 c1 = *(const float2*)(rB + 20 + j0);
        float2 c2 = *(const float2*)(rB + 40 + j0);
        xwzA = pk(a0.x, a0.y); xwrA = pk(a1.x, a1.y); xwhA = f2add(pk(a2.x, a2.y), bh0i2);
        xwzB = pk(c0.x, c0.y); xwrB = pk(c1.x, c1.y); xwhB = f2add(pk(c2.x, c2.y), bh0i2);
    }

    int cur = 0;
    for (int t = 0; t < T_; t++) {
        // ---------------- layer 0 ----------------
        const ulonglong2* hA = (const ulonglong2*)&h0d[cur][cA][0];
        const ulonglong2* hB = (const ulonglong2*)&h0d[cur][cB][0];
        u64 azA = zc0, arA = rc0, ahA = bh0r2;
        u64 azB = zc0, arB = rc0, ahB = bh0r2;
        #pragma unroll
        for (int kk = 0; kk < 10; kk++) {
            ulonglong2 wz = pWz[kk], wr = pWr[kk], wh = pWh[kk];
            ulonglong2 ha = hA[kk], hb = hB[kk];
            azA = f2fma(ha.x, wz.x, azA); azA = f2fma(ha.y, wz.y, azA);
            arA = f2fma(ha.x, wr.x, arA); arA = f2fma(ha.y, wr.y, arA);
            ahA = f2fma(ha.x, wh.x, ahA); ahA = f2fma(ha.y, wh.y, ahA);
            azB = f2fma(hb.x, wz.x, azB); azB = f2fma(hb.y, wz.y, azB);
            arB = f2fma(hb.x, wr.x, arB); arB = f2fma(hb.y, wr.y, arB);
            ahB = f2fma(hb.x, wh.x, ahB); ahB = f2fma(hb.y, wh.y, ahB);
        }
        {
            float z0,z1,r0,r1,p0,p1,q0,q1;
            upk(z0,z1, f2add(azA, xwzA)); upk(r0,r1, f2add(arA, xwrA));
            z0 = fsigm(z0); z1 = fsigm(z1); r0 = fsigm(r0); r1 = fsigm(r1);
            upk(p0,p1, ahA); upk(q0,q1, xwhA);
            float g0 = ftanh_(q0 + r0 * p0), g1 = ftanh_(q1 + r1 * p1);
            float n0 = g0 + z0 * (h0A0 - g0), n1 = g1 + z1 * (h0A1 - g1);
            h0A0 = n0; h0A1 = n1;
            ulonglong2 st; st.x = pk(n0, n0); st.y = pk(n1, n1);
            *(ulonglong2*)&h0d[cur ^ 1][cA][j0] = st;
        }
        {
            float z0,z1,r0,r1,p0,p1,q0,q1;
            upk(z0,z1, f2add(azB, xwzB)); upk(r0,r1, f2add(arB, xwrB));
            z0 = fsigm(z0); z1 = fsigm(z1); r0 = fsigm(r0); r1 = fsigm(r1);
            upk(p0,p1, ahB); upk(q0,q1, xwhB);
            float g0 = ftanh_(q0 + r0 * p0), g1 = ftanh_(q1 + r1 * p1);
            float n0 = g0 + z0 * (h0B0 - g0), n1 = g1 + z1 * (h0B1 - g1);
            h0B0 = n0; h0B1 = n1;
            ulonglong2 st; st.x = pk(n0, n0); st.y = pk(n1, n1);
            *(ulonglong2*)&h0d[cur ^ 1][cB][j0] = st;
        }
        __syncwarp();

        if (t + 1 < T_) {
            const float* rA = W0 + xs[cA][t + 1] * G3_;
            const float* rB = W0 + xs[cB][t + 1] * G3_;
            float2 a0 = *(const float2*)(rA + j0);
            float2 a1 = *(const float2*)(rA + 20 + j0);
            float2 a2 = *(const float2*)(rA + 40 + j0);
            float2 c0 = *(const float2*)(rB + j0);
            float2 c1 = *(const float2*)(rB + 20 + j0);
            float2 c2 = *(const float2*)(rB + 40 + j0);
            xwzA = pk(a0.x, a0.y); xwrA = pk(a1.x, a1.y); xwhA = f2add(pk(a2.x, a2.y), bh0i2);
            xwzB = pk(c0.x, c0.y); xwrB = pk(c1.x, c1.y); xwhB = f2add(pk(c2.x, c2.y), bh0i2);
        }

        // ---------------- layer 1 ----------------
        const ulonglong2* gA = (const ulonglong2*)&h0d[cur ^ 1][cA][0];
        const ulonglong2* gB = (const ulonglong2*)&h0d[cur ^ 1][cB][0];
        const ulonglong2* qA = (const ulonglong2*)&h1d[cur][cA][0];
        const ulonglong2* qB = (const ulonglong2*)&h1d[cur][cB][0];
        u64 xzA = zc1, xrA = rc1, xhA = bxh1, rzA = 0ull, rrA = 0ull, rhA = brh1;
        u64 xzB = zc1, xrB = rc1, xhB = bxh1, rzB = 0ull, rrB = 0ull, rhB = brh1;
        #pragma unroll
        for (int kk = 0; kk < 10; kk++) {
            ulonglong2 vz = pVz[kk], vr = pVr[kk], vh = pVh[kk];
            ulonglong2 uz = pUz[kk], ur = pUr[kk], uh = pUh[kk];
            ulonglong2 ga = gA[kk], gb = gB[kk];
            ulonglong2 qa = qA[kk], qb = qB[kk];
            xzA = f2fma(ga.x, vz.x, xzA); xzA = f2fma(ga.y, vz.y, xzA);
            xrA = f2fma(ga.x, vr.x, xrA); xrA = f2fma(ga.y, vr.y, xrA);
            xhA = f2fma(ga.x, vh.x, xhA); xhA = f2fma(ga.y, vh.y, xhA);
            rzA = f2fma(qa.x, uz.x, rzA); rzA = f2fma(qa.y, uz.y, rzA);
            rrA = f2fma(qa.x, ur.x, rrA); rrA = f2fma(qa.y, ur.y, rrA);
            rhA = f2fma(qa.x, uh.x, rhA); rhA = f2fma(qa.y, uh.y, rhA);
            xzB = f2fma(gb.x, vz.x, xzB); xzB = f2fma(gb.y, vz.y, xzB);
            xrB = f2fma(gb.x, vr.x, xrB); xrB = f2fma(gb.y, vr.y, xrB);
            xhB = f2fma(gb.x, vh.x, xhB); xhB = f2fma(gb.y, vh.y, xhB);
            rzB = f2fma(qb.x, uz.x, rzB); rzB = f2fma(qb.y, uz.y, rzB);
            rrB = f2fma(qb.x, ur.x, rrB); rrB = f2fma(qb.y, ur.y, rrB);
            rhB = f2fma(qb.x, uh.x, rhB); rhB = f2fma(qb.y, uh.y, rhB);
        }
        {
            float z0,z1,r0,r1,p0,p1,q0,q1;
            upk(z0,z1, f2add(xzA, rzA)); upk(r0,r1, f2add(xrA, rrA));
            z0 = fsigm(z0); z1 = fsigm(z1); r0 = fsigm(r0); r1 = fsigm(r1);
            upk(p0,p1, rhA); upk(q0,q1, xhA);
            float g0 = ftanh_(q0 + r0 * p0), g1 = ftanh_(q1 + r1 * p1);
            float n0 = g0 + z0 * (h1A0 - g0), n1 = g1 + z1 * (h1A1 - g1);
            h1A0 = n0; h1A1 = n1;
            ulonglong2 st; st.x = pk(n0, n0); st.y = pk(n1, n1);
            *(ulonglong2*)&h1d[cur ^ 1][cA][j0] = st;
        }
        {
            float z0,z1,r0,r1,p0,p1,q0,q1;
            upk(z0,z1, f2add(xzB, rzB)); upk(r0,r1, f2add(xrB, rrB));
            z0 = fsigm(z0); z1 = fsigm(z1); r0 = fsigm(r0); r1 = fsigm(r1);
            upk(p0,p1, rhB); upk(q0,q1, xhB);
            float g0 = ftanh_(q0 + r0 * p0), g1 = ftanh_(q1 + r1 * p1);
            float n0 = g0 + z0 * (h1B0 - g0), n1 = g1 + z1 * (h1B1 - g1);
            h1B0 = n0; h1B1 = n1;
            ulonglong2 st; st.x = pk(n0, n0); st.y = pk(n1, n1);
            *(ulonglong2*)&h1d[cur ^ 1][cB][j0] = st;
        }
        __syncwarp();
        cur ^= 1;
    }

    // ---------------- dense + softmax ----------------
    if (lane < L_) {
        float a0 = bd[lane], a1 = a0, a2 = a0, a3 = a0;
        const float* p0 = (const float*)&h1d[cur][0][0];
        const float* p1 = (const float*)&h1d[cur][1][0];
        const float* p2 = (const float*)&h1d[cur][2][0];
        const float* p3 = (const float*)&h1d[cur][3][0];
        #pragma unroll
        for (int k = 0; k < H_; k++) {
            float wdk = Wd[k * L_ + lane];
            a0 = fmaf(p0[2 * k], wdk, a0);
            a1 = fmaf(p1[2 * k], wdk, a1);
            a2 = fmaf(p2[2 * k], wdk, a2);
            a3 = fmaf(p3[2 * k], wdk, a3);
        }
        lgs[0][lane] = a0; lgs[1][lane] = a1; lgs[2][lane] = a2; lgs[3][lane] = a3;
    }
    __syncwarp();
    if (lane < L_) {
        #pragma unroll
        for (int c = 0; c < NBW; c++) {
            float m = lgs[c][0];
            #pragma unroll
            for (int l = 1; l < L_; l++) m = fmaxf(m, lgs[c][l]);
            float s = 0.f;
            #pragma unroll
            for (int l = 0; l < L_; l++) s += __expf(lgs[c][l] - m);
            out[(b0g + c) * L_ + lane] = __fdividef(__expf(lgs[c][lane] - m), s);
        }
    }
}

extern "C" void kernel_launch(void* const* d_in, const int* in_sizes, int n_in,
                              void* d_out, int out_size)
{
    (void)in_sizes; (void)n_in; (void)out_size;
    const int*   x   = (const int*)  d_in[0];
    const float* W0  = (const float*)d_in[1];
    const float* U0  = (const float*)d_in[2];
    const float* b0i = (const float*)d_in[3];
    const float* b0r = (const float*)d_in[4];
    const float* W1  = (const float*)d_in[5];
    const float* U1  = (const float*)d_in[6];
    const float* b1i = (const float*)d_in[7];
    const float* b1r = (const float*)d_in[8];
    const float* Wd  = (const float*)d_in[9];
    const float* bd  = (const float*)d_in[10];
    float* out = (float*)d_out;

    gru2_kernel<<<GRID, 32>>>(x, W0, U0, b0i, b0r, W1, U1, b1i, b1r, Wd, bd, out);
}

// round 10
// speedup vs baseline: 1.6476x; 1.6476x over previous
#include <cuda_runtime.h>

#define B_   2048
#define T_   128
#define V_   256
#define H_   20
#define G3_  60
#define L_   15
#define NPAIR 2
#define NB    4                 // batches per block (2 pairs)
#define NTHR  (NPAIR * H_)      // 40 threads: p = tid&1, j = tid>>1
#define WPAD  22                // u64 row stride (176B): per-warp j starts spread banks

typedef unsigned long long u64;

__device__ __forceinline__ u64 pk(float lo, float hi) {
    u64 r; asm("mov.b64 %0,{%1,%2};" : "=l"(r) : "f"(lo), "f"(hi)); return r;
}
__device__ __forceinline__ void upk(float& lo, float& hi, u64 v) {
    asm("mov.b64 {%0,%1},%2;" : "=f"(lo), "=f"(hi) : "l"(v));
}
__device__ __forceinline__ u64 f2fma(u64 a, u64 b, u64 c) {
    u64 d; asm("fma.rn.f32x2 %0,%1,%2,%3;" : "=l"(d) : "l"(a), "l"(b), "l"(c)); return d;
}
__device__ __forceinline__ u64 f2add(u64 a, u64 b) {
    u64 d; asm("add.rn.f32x2 %0,%1,%2;" : "=l"(d) : "l"(a), "l"(b)); return d;
}
__device__ __forceinline__ float tanhapx(float x) {
    float y; asm("tanh.approx.f32 %0, %1;" : "=f"(y) : "f"(x)); return y;
}
__device__ __forceinline__ float fsigm(float x) {
    // sigma(x) = 0.5 + 0.5*tanh(x/2)  (1 MUFU + 2 FMA-class ops)
    return fmaf(0.5f, tanhapx(0.5f * x), 0.5f);
}

__global__ __launch_bounds__(NTHR, 4)
void gru2_kernel(const int* __restrict__ x,
                 const float* __restrict__ W0, const float* __restrict__ U0,
                 const float* __restrict__ b0i, const float* __restrict__ b0r,
                 const float* __restrict__ W1, const float* __restrict__ U1,
                 const float* __restrict__ b1i, const float* __restrict__ b1r,
                 const float* __restrict__ Wd, const float* __restrict__ bd,
                 float* __restrict__ out)
{
    // Dup-packed weights {w,w}: [gate][j][k(padded)], k contiguous.
    __shared__ alignas(16) u64 U0d[3][H_][WPAD];
    __shared__ alignas(16) u64 W1d[3][H_][WPAD];
    __shared__ alignas(16) u64 U1d[3][H_][WPAD];
    // Packed hidden state: pair p holds batches (p, p+2)
    __shared__ alignas(16) u64 h0buf[2][NPAIR][WPAD];
    __shared__ alignas(16) u64 h1buf[2][NPAIR][WPAD];
    __shared__ int   xs[NB][T_];
    __shared__ float lg[NB][L_];

    const int tid = threadIdx.x;
    const int p   = tid & (NPAIR - 1);
    const int j   = tid >> 1;               // 0..19
    const int bg  = blockIdx.x * NB;

    // ---- setup: duplicate weights into shared ----
    for (int idx = tid; idx < 3 * H_ * H_; idx += NTHR) {
        int g = idx / (H_ * H_);
        int r = idx % (H_ * H_);
        int jj = r / H_, k = r % H_;
        float w0 = U0[k * G3_ + g * H_ + jj]; U0d[g][jj][k] = pk(w0, w0);
        float w1 = W1[k * G3_ + g * H_ + jj]; W1d[g][jj][k] = pk(w1, w1);
        float u1 = U1[k * G3_ + g * H_ + jj]; U1d[g][jj][k] = pk(u1, u1);
    }
    for (int idx = tid; idx < NB * T_; idx += NTHR) {
        int bb = idx >> 7, t = idx & (T_ - 1);
        xs[bb][t] = x[(bg + bb) * T_ + t];
    }
    h0buf[0][p][j] = 0ull; h0buf[1][p][j] = 0ull;
    h1buf[0][p][j] = 0ull; h1buf[1][p][j] = 0ull;

    // bias registers
    const float bz0i = b0i[j], br0i = b0i[20 + j], bh0i = b0i[40 + j];
    const u64   bz0r2 = pk(b0r[j], b0r[j]);
    const u64   br0r2 = pk(b0r[20 + j], b0r[20 + j]);
    const u64   bh0r2 = pk(b0r[40 + j], b0r[40 + j]);
    const u64   bz1i2 = pk(b1i[j], b1i[j]);
    const u64   br1i2 = pk(b1i[20 + j], b1i[20 + j]);
    const u64   bh1i2 = pk(b1i[40 + j], b1i[40 + j]);
    const u64   bz1r2 = pk(b1r[j], b1r[j]);
    const u64   br1r2 = pk(b1r[20 + j], b1r[20 + j]);
    const u64   bh1r2 = pk(b1r[40 + j], b1r[40 + j]);
    __syncthreads();

    const ulonglong2* wz = (const ulonglong2*)U0d[0][j];
    const ulonglong2* wr = (const ulonglong2*)U0d[1][j];
    const ulonglong2* wh = (const ulonglong2*)U0d[2][j];
    const ulonglong2* vz = (const ulonglong2*)W1d[0][j];
    const ulonglong2* vr = (const ulonglong2*)W1d[1][j];
    const ulonglong2* vh = (const ulonglong2*)W1d[2][j];
    const ulonglong2* uz = (const ulonglong2*)U1d[0][j];
    const ulonglong2* ur = (const ulonglong2*)U1d[1][j];
    const ulonglong2* uh = (const ulonglong2*)U1d[2][j];

    // prefetch W0 gather rows for t = 0
    float xwzA, xwzB, xwrA, xwrB, xwhA, xwhB;
    {
        const float* wA = W0 + xs[p][0] * G3_;
        const float* wB = W0 + xs[p + NPAIR][0] * G3_;
        xwzA = wA[j];      xwzB = wB[j];
        xwrA = wA[20 + j]; xwrB = wB[20 + j];
        xwhA = wA[40 + j]; xwhB = wB[40 + j];
    }

    int cur = 0;
    for (int t = 0; t < T_; t++) {
        // ================= layer 0 =================
        const ulonglong2* hp = (const ulonglong2*)h0buf[cur][p];
        u64 az0 = bz0r2, az1 = 0ull;
        u64 ar0 = br0r2, ar1 = 0ull;
        u64 ah0 = bh0r2, ah1 = 0ull;
        #pragma unroll
        for (int kk = 0; kk < H_ / 2; kk++) {
            ulonglong2 h2 = hp[kk];
            ulonglong2 z2 = wz[kk], r2 = wr[kk], g2 = wh[kk];
            az0 = f2fma(h2.x, z2.x, az0); az1 = f2fma(h2.y, z2.y, az1);
            ar0 = f2fma(h2.x, r2.x, ar0); ar1 = f2fma(h2.y, r2.y, ar1);
            ah0 = f2fma(h2.x, g2.x, ah0); ah1 = f2fma(h2.y, g2.y, ah1);
        }
        float azA, azB, arA, arB, ahA, ahB;
        upk(azA, azB, f2add(az0, az1));
        upk(arA, arB, f2add(ar0, ar1));
        upk(ahA, ahB, f2add(ah0, ah1));

        float zA = fsigm(xwzA + bz0i + azA);
        float zB = fsigm(xwzB + bz0i + azB);
        float rA = fsigm(xwrA + br0i + arA);
        float rB = fsigm(xwrB + br0i + arB);
        float gA = tanhapx(xwhA + bh0i + rA * ahA);
        float gB = tanhapx(xwhB + bh0i + rB * ahB);
        float hA, hB; upk(hA, hB, h0buf[cur][p][j]);
        float h0nA = gA + zA * (hA - gA);
        float h0nB = gB + zB * (hB - gB);
        h0buf[cur ^ 1][p][j] = pk(h0nA, h0nB);
        __syncthreads();

        // -------- prefetch W0 gather for t+1 ----
        if (t + 1 < T_) {
            const float* wA = W0 + xs[p][t + 1] * G3_;
            const float* wB = W0 + xs[p + NPAIR][t + 1] * G3_;
            xwzA = wA[j];      xwzB = wB[j];
            xwrA = wA[20 + j]; xwrB = wB[20 + j];
            xwhA = wA[40 + j]; xwhB = wB[40 + j];
        }

        // ================= layer 1 =================
        const ulonglong2* h0p = (const ulonglong2*)h0buf[cur ^ 1][p];
        const ulonglong2* h1p = (const ulonglong2*)h1buf[cur][p];
        u64 xz = bz1i2, xr = br1i2, xh = bh1i2;
        u64 rz = bz1r2, rr = br1r2, rh = bh1r2;
        #pragma unroll
        for (int kk = 0; kk < H_ / 2; kk++) {
            ulonglong2 a2 = h0p[kk];
            ulonglong2 b2 = h1p[kk];
            ulonglong2 wz2 = vz[kk], wr2 = vr[kk], wh2 = vh[kk];
            ulonglong2 uz2 = uz[kk], ur2 = ur[kk], uh2 = uh[kk];
            xz = f2fma(a2.x, wz2.x, xz); xz = f2fma(a2.y, wz2.y, xz);
            xr = f2fma(a2.x, wr2.x, xr); xr = f2fma(a2.y, wr2.y, xr);
            xh = f2fma(a2.x, wh2.x, xh); xh = f2fma(a2.y, wh2.y, xh);
            rz = f2fma(b2.x, uz2.x, rz); rz = f2fma(b2.y, uz2.y, rz);
            rr = f2fma(b2.x, ur2.x, rr); rr = f2fma(b2.y, ur2.y, rr);
            rh = f2fma(b2.x, uh2.x, rh); rh = f2fma(b2.y, uh2.y, rh);
        }
        float xzA, xzB, xrA, xrB, xhA, xhB, rzA, rzB, rrA, rrB, rhA, rhB;
        upk(xzA, xzB, xz); upk(xrA, xrB, xr); upk(xhA, xhB, xh);
        upk(rzA, rzB, rz); upk(rrA, rrB, rr); upk(rhA, rhB, rh);
        float z1A = fsigm(xzA + rzA);
        float z1B = fsigm(xzB + rzB);
        float r1A = fsigm(xrA + rrA);
        float r1B = fsigm(xrB + rrB);
        float g1A = tanhapx(xhA + r1A * rhA);
        float g1B = tanhapx(xhB + r1B * rhB);
        float q1A, q1B; upk(q1A, q1B, h1buf[cur][p][j]);
        float h1nA = g1A + z1A * (q1A - g1A);
        float h1nB = g1B + z1B * (q1B - g1B);
        h1buf[cur ^ 1][p][j] = pk(h1nA, h1nB);
        __syncthreads();
        cur ^= 1;
    }

    // ================= dense + softmax (both batches per thread) =================
    if (j < L_ && p == 0) {
        #pragma unroll
        for (int c = 0; c < NPAIR; c++) {
            float accA = bd[j], accB = bd[j];
            #pragma unroll
            for (int k = 0; k < H_; k++) {
                float wdk = Wd[k * L_ + j];
                float hl, hh; upk(hl, hh, h1buf[cur][c][k]);
                accA = fmaf(hl, wdk, accA);
                accB = fmaf(hh, wdk, accB);
            }
            lg[c][j] = accA;
            lg[c + NPAIR][j] = accB;
        }
    }
    __syncthreads();
    if (j < L_ && p == 0) {
        #pragma unroll
        for (int c = 0; c < NB; c++) {
            float m = lg[c][0];
            #pragma unroll
            for (int l = 1; l < L_; l++) m = fmaxf(m, lg[c][l]);
            float s = 0.f;
            #pragma unroll
            for (int l = 0; l < L_; l++) s += __expf(lg[c][l] - m);
            out[(bg + c) * L_ + j] = __fdividef(__expf(lg[c][j] - m), s);
        }
    }
}

extern "C" void kernel_launch(void* const* d_in, const int* in_sizes, int n_in,
                              void* d_out, int out_size)
{
    (void)in_sizes; (void)n_in; (void)out_size;
    const int*   x   = (const int*)  d_in[0];
    const float* W0  = (const float*)d_in[1];
    const float* U0  = (const float*)d_in[2];
    const float* b0i = (const float*)d_in[3];
    const float* b0r = (const float*)d_in[4];
    const float* W1  = (const float*)d_in[5];
    const float* U1  = (const float*)d_in[6];
    const float* b1i = (const float*)d_in[7];
    const float* b1r = (const float*)d_in[8];
    const float* Wd  = (const float*)d_in[9];
    const float* bd  = (const float*)d_in[10];
    float* out = (float*)d_out;

    gru2_kernel<<<B_ / NB, NTHR>>>(x, W0, U0, b0i, b0r, W1, U1, b1i, b1r, Wd, bd, out);
}

// round 16
// speedup vs baseline: 1.6628x; 1.0092x over previous
#include <cuda_runtime.h>

#define B_   2048
#define T_   128
#define V_   256
#define H_   20
#define G3_  60
#define L_   15
#define NPAIR 2
#define NB    4                 // batches per block (2 pairs)
#define NTHR  (NPAIR * H_)      // 40 threads: p = tid&1, j = tid>>1
#define WPAD  22                // u64 row stride (176B)

typedef unsigned long long u64;

__device__ __forceinline__ u64 pk(float lo, float hi) {
    u64 r; asm("mov.b64 %0,{%1,%2};" : "=l"(r) : "f"(lo), "f"(hi)); return r;
}
__device__ __forceinline__ void upk(float& lo, float& hi, u64 v) {
    asm("mov.b64 {%0,%1},%2;" : "=f"(lo), "=f"(hi) : "l"(v));
}
__device__ __forceinline__ u64 f2fma(u64 a, u64 b, u64 c) {
    u64 d; asm("fma.rn.f32x2 %0,%1,%2,%3;" : "=l"(d) : "l"(a), "l"(b), "l"(c)); return d;
}
__device__ __forceinline__ u64 f2add(u64 a, u64 b) {
    u64 d; asm("add.rn.f32x2 %0,%1,%2;" : "=l"(d) : "l"(a), "l"(b)); return d;
}
__device__ __forceinline__ float tanhapx(float x) {
    float y; asm("tanh.approx.f32 %0, %1;" : "=f"(y) : "f"(x)); return y;
}
__device__ __forceinline__ float fsigm(float x) {
    return fmaf(0.5f, tanhapx(0.5f * x), 0.5f);
}

__global__ __launch_bounds__(NTHR, 4)
void gru2_kernel(const int* __restrict__ x,
                 const float* __restrict__ W0, const float* __restrict__ U0,
                 const float* __restrict__ b0i, const float* __restrict__ b0r,
                 const float* __restrict__ W1, const float* __restrict__ U1,
                 const float* __restrict__ b1i, const float* __restrict__ b1r,
                 const float* __restrict__ Wd, const float* __restrict__ bd,
                 float* __restrict__ out)
{
    __shared__ alignas(16) u64 U0d[3][H_][WPAD];
    __shared__ alignas(16) u64 W1d[3][H_][WPAD];
    __shared__ alignas(16) u64 U1d[3][H_][WPAD];
    // single-buffered packed hidden rows: pair p holds batches (p, p+2)
    __shared__ alignas(16) u64 h0row[NPAIR][WPAD];
    __shared__ alignas(16) u64 h1row[NPAIR][WPAD];
    __shared__ int   xs[NB][T_];
    __shared__ float lg[NB][L_];

    const int tid = threadIdx.x;
    const int p   = tid & (NPAIR - 1);
    const int j   = tid >> 1;               // 0..19
    const int bg  = blockIdx.x * NB;

    for (int idx = tid; idx < 3 * H_ * H_; idx += NTHR) {
        int g = idx / (H_ * H_);
        int r = idx % (H_ * H_);
        int jj = r / H_, k = r % H_;
        float w0 = U0[k * G3_ + g * H_ + jj]; U0d[g][jj][k] = pk(w0, w0);
        float w1 = W1[k * G3_ + g * H_ + jj]; W1d[g][jj][k] = pk(w1, w1);
        float u1 = U1[k * G3_ + g * H_ + jj]; U1d[g][jj][k] = pk(u1, u1);
    }
    for (int idx = tid; idx < NB * T_; idx += NTHR) {
        int bb = idx >> 7, t = idx & (T_ - 1);
        xs[bb][t] = x[(bg + bb) * T_ + t];
    }
    h1row[p][j] = 0ull;   // h0row is written in Phase A before any read

    // biases
    const u64 bz0i2 = pk(b0i[j], b0i[j]);
    const u64 br0i2 = pk(b0i[20 + j], b0i[20 + j]);
    const u64 bh0i2 = pk(b0i[40 + j], b0i[40 + j]);
    const u64 bz0r2 = pk(b0r[j], b0r[j]);
    const u64 br0r2 = pk(b0r[20 + j], b0r[20 + j]);
    const u64 bh0r2 = pk(b0r[40 + j], b0r[40 + j]);
    const u64 bz1i2 = pk(b1i[j], b1i[j]);
    const u64 br1i2 = pk(b1i[20 + j], b1i[20 + j]);
    const u64 bh1i2 = pk(b1i[40 + j], b1i[40 + j]);
    const u64 bz1r2 = pk(b1r[j], b1r[j]);
    const u64 br1r2 = pk(b1r[20 + j], b1r[20 + j]);
    const u64 bh1r2 = pk(b1r[40 + j], b1r[40 + j]);
    __syncthreads();

    const ulonglong2* wz = (const ulonglong2*)U0d[0][j];
    const ulonglong2* wr = (const ulonglong2*)U0d[1][j];
    const ulonglong2* wh = (const ulonglong2*)U0d[2][j];
    const ulonglong2* vz = (const ulonglong2*)W1d[0][j];
    const ulonglong2* vr = (const ulonglong2*)W1d[1][j];
    const ulonglong2* vh = (const ulonglong2*)W1d[2][j];
    const ulonglong2* uz = (const ulonglong2*)U1d[0][j];
    const ulonglong2* ur = (const ulonglong2*)U1d[1][j];
    const ulonglong2* uh = (const ulonglong2*)U1d[2][j];

    // carried state: precomputed U0·h0 sums (h0 = 0 at t=0 -> just recurrent biases)
    u64 sU0z = bz0r2, sU0r = br0r2, sU0h = bh0r2;
    float h0A = 0.f, h0B = 0.f, h1A = 0.f, h1B = 0.f;

    // prefetch xW0 for t = 0, packed {A,B}, input bias folded
    u64 xwz2, xwr2, xwh2;
    {
        const float* wA = W0 + xs[p][0] * G3_;
        const float* wB = W0 + xs[p + NPAIR][0] * G3_;
        xwz2 = f2add(pk(wA[j],      wB[j]),      bz0i2);
        xwr2 = f2add(pk(wA[20 + j], wB[20 + j]), br0i2);
        xwh2 = f2add(pk(wA[40 + j], wB[40 + j]), bh0i2);
    }

    for (int t = 0; t < T_; t++) {
        // ================= Phase A =================
        // layer-0 activations: inputs already in registers
        float zA, zB, rA, rB, ahA, ahB, xhA, xhB;
        {
            float a0, a1;
            upk(a0, a1, f2add(xwz2, sU0z)); zA = fsigm(a0); zB = fsigm(a1);
            upk(a0, a1, f2add(xwr2, sU0r)); rA = fsigm(a0); rB = fsigm(a1);
            upk(ahA, ahB, sU0h); upk(xhA, xhB, xwh2);
        }
        float gA = tanhapx(xhA + rA * ahA);
        float gB = tanhapx(xhB + rB * ahB);
        float h0nA = gA + zA * (h0A - gA);
        float h0nB = gB + zB * (h0B - gB);
        h0A = h0nA; h0B = h0nB;
        h0row[p][j] = pk(h0nA, h0nB);

        // U1·h1(t-1): independent, overlaps the activation chain above
        // (full H: 10 ulonglong2 = 20 u64 elements)
        u64 rz0 = bz1r2, rz1 = 0ull, rr0 = br1r2, rr1 = 0ull, rh0 = bh1r2, rh1 = 0ull;
        {
            const ulonglong2* h1p = (const ulonglong2*)h1row[p];
            #pragma unroll
            for (int kk = 0; kk < H_ / 2; kk++) {
                ulonglong2 b2 = h1p[kk];
                ulonglong2 uz2 = uz[kk], ur2 = ur[kk], uh2 = uh[kk];
                rz0 = f2fma(b2.x, uz2.x, rz0); rz1 = f2fma(b2.y, uz2.y, rz1);
                rr0 = f2fma(b2.x, ur2.x, rr0); rr1 = f2fma(b2.y, ur2.y, rr1);
                rh0 = f2fma(b2.x, uh2.x, rh0); rh1 = f2fma(b2.y, uh2.y, rh1);
            }
        }
        u64 ruz = f2add(rz0, rz1), rur = f2add(rr0, rr1), ruh = f2add(rh0, rh1);

        // prefetch xW0 for t+1
        if (t + 1 < T_) {
            const float* wA = W0 + xs[p][t + 1] * G3_;
            const float* wB = W0 + xs[p + NPAIR][t + 1] * G3_;
            xwz2 = f2add(pk(wA[j],      wB[j]),      bz0i2);
            xwr2 = f2add(pk(wA[20 + j], wB[20 + j]), br0i2);
            xwh2 = f2add(pk(wA[40 + j], wB[40 + j]), bh0i2);
        }
        __syncthreads();

        // ================= Phase B =================
        // load full h0 row once; feed both W1 and the U0 precompute
        ulonglong2 hh[H_ / 2];
        {
            const ulonglong2* h0p = (const ulonglong2*)h0row[p];
            #pragma unroll
            for (int kk = 0; kk < H_ / 2; kk++) hh[kk] = h0p[kk];
        }
        // W1·h0(t)
        u64 xz0 = bz1i2, xz1 = 0ull, xr0 = br1i2, xr1 = 0ull, xh0 = bh1i2, xh1 = 0ull;
        #pragma unroll
        for (int kk = 0; kk < H_ / 2; kk++) {
            ulonglong2 a2 = hh[kk];
            ulonglong2 vz2 = vz[kk], vr2 = vr[kk], vh2 = vh[kk];
            xz0 = f2fma(a2.x, vz2.x, xz0); xz1 = f2fma(a2.y, vz2.y, xz1);
            xr0 = f2fma(a2.x, vr2.x, xr0); xr1 = f2fma(a2.y, vr2.y, xr1);
            xh0 = f2fma(a2.x, vh2.x, xh0); xh1 = f2fma(a2.y, vh2.y, xh1);
        }
        // layer-1 activations
        {
            float a0, a1, b0, b1;
            upk(a0, a1, f2add(f2add(xz0, xz1), ruz));
            float z1A = fsigm(a0), z1B = fsigm(a1);
            upk(a0, a1, f2add(f2add(xr0, xr1), rur));
            float r1A = fsigm(a0), r1B = fsigm(a1);
            upk(a0, a1, ruh);
            upk(b0, b1, f2add(xh0, xh1));
            float g1A = tanhapx(b0 + r1A * a0);
            float g1B = tanhapx(b1 + r1B * a1);
            float h1nA = g1A + z1A * (h1A - g1A);
            float h1nB = g1B + z1B * (h1B - g1B);
            h1A = h1nA; h1B = h1nB;
            h1row[p][j] = pk(h1nA, h1nB);
        }
        // U0·h0(t) precompute for next step (independent filler work)
        {
            u64 az0 = bz0r2, az1 = 0ull, ar0 = br0r2, ar1 = 0ull, ah0 = bh0r2, ah1 = 0ull;
            #pragma unroll
            for (int kk = 0; kk < H_ / 2; kk++) {
                ulonglong2 a2 = hh[kk];
                ulonglong2 z2 = wz[kk], r2 = wr[kk], g2 = wh[kk];
                az0 = f2fma(a2.x, z2.x, az0); az1 = f2fma(a2.y, z2.y, az1);
                ar0 = f2fma(a2.x, r2.x, ar0); ar1 = f2fma(a2.y, r2.y, ar1);
                ah0 = f2fma(a2.x, g2.x, ah0); ah1 = f2fma(a2.y, g2.y, ah1);
            }
            sU0z = f2add(az0, az1);
            sU0r = f2add(ar0, ar1);
            sU0h = f2add(ah0, ah1);
        }
        __syncthreads();
    }

    // ================= dense + softmax =================
    if (j < L_ && p == 0) {
        #pragma unroll
        for (int c = 0; c < NPAIR; c++) {
            float accA = bd[j], accB = bd[j];
            #pragma unroll
            for (int k = 0; k < H_; k++) {
                float wdk = Wd[k * L_ + j];
                float hl, hh2; upk(hl, hh2, h1row[c][k]);
                accA = fmaf(hl, wdk, accA);
                accB = fmaf(hh2, wdk, accB);
            }
            lg[c][j] = accA;
            lg[c + NPAIR][j] = accB;
        }
    }
    __syncthreads();
    if (j < L_ && p == 0) {
        #pragma unroll
        for (int c = 0; c < NB; c++) {
            float m = lg[c][0];
            #pragma unroll
            for (int l = 1; l < L_; l++) m = fmaxf(m, lg[c][l]);
            float s = 0.f;
            #pragma unroll
            for (int l = 0; l < L_; l++) s += __expf(lg[c][l] - m);
            out[(bg + c) * L_ + j] = __fdividef(__expf(lg[c][j] - m), s);
        }
    }
}

extern "C" void kernel_launch(void* const* d_in, const int* in_sizes, int n_in,
                              void* d_out, int out_size)
{
    (void)in_sizes; (void)n_in; (void)out_size;
    const int*   x   = (const int*)  d_in[0];
    const float* W0  = (const float*)d_in[1];
    const float* U0  = (const float*)d_in[2];
    const float* b0i = (const float*)d_in[3];
    const float* b0r = (const float*)d_in[4];
    const float* W1  = (const float*)d_in[5];
    const float* U1  = (const float*)d_in[6];
    const float* b1i = (const float*)d_in[7];
    const float* b1r = (const float*)d_in[8];
    const float* Wd  = (const float*)d_in[9];
    const float* bd  = (const float*)d_in[10];
    float* out = (float*)d_out;

    gru2_kernel<<<B_ / NB, NTHR>>>(x, W0, U0, b0i, b0r, W1, U1, b1i, b1r, Wd, bd, out);
}